// round 16
// baseline (speedup 1.0000x reference)
#include <cuda_runtime.h>
#include <cuda_fp16.h>
#include <cstdint>

// Shapes
#define B_    16
#define H_    128
#define W_    128
#define RDIM  4
#define ACT   8
#define KK    45      // logit/patch dim
#define KPAD  48      // padded K (3 k-tiles of 16)
#define JPAD  48      // padded rows per action (6 n-tiles of 8)
#define MPIX  256     // pixels per CTA (2 image rows)

// SMEM layout (bytes). Strides chosen for conflict-free fragment access.
#define ASTR   112                  // fp16 A row stride
#define BSTR   112                  // fp16 B row stride (56 halfs)
#define OFF_A  0
#define OFF_B  (OFF_A + MPIX*ASTR)  // 28672
#define SZ_B   (ACT*JPAD*BSTR)      // 43008
#define SM_END (OFF_B + SZ_B)       // 71680 B
#define BHALF  (SZ_B/2)             // 21504 halfs

#define LOG2E 1.4426950408889634f

// Pre-built padded fp16 weight image (exact SMEM B-region layout)
__device__ __align__(16) unsigned char g_wf16[SZ_B];

__device__ __forceinline__ void mma_f16(float d[4], const uint32_t a[4],
                                        uint32_t b0, uint32_t b1) {
    asm volatile(
        "mma.sync.aligned.m16n8k16.row.col.f32.f16.f16.f32 "
        "{%0,%1,%2,%3}, {%4,%5,%6,%7}, {%8,%9}, {%0,%1,%2,%3};"
        : "+f"(d[0]), "+f"(d[1]), "+f"(d[2]), "+f"(d[3])
        : "r"(a[0]), "r"(a[1]), "r"(a[2]), "r"(a[3]), "r"(b0), "r"(b1));
}

__device__ __forceinline__ void ldsm_x4(uint32_t r[4], uint32_t addr) {
    asm volatile("ldmatrix.sync.aligned.m8n8.x4.shared.b16 {%0,%1,%2,%3}, [%4];"
                 : "=r"(r[0]), "=r"(r[1]), "=r"(r[2]), "=r"(r[3]) : "r"(addr));
}

__device__ __forceinline__ uint32_t smem_u32(const void* p) {
    uint32_t a;
    asm("{ .reg .u64 t; cvta.to.shared.u64 t, %1; cvt.u32.u64 %0, t; }" : "=r"(a) : "l"(p));
    return a;
}

// pack two f32 into f16x2 (lo, hi); PTX: first source -> high half
__device__ __forceinline__ uint32_t pack_f16x2(float lo, float hi) {
    uint32_t r;
    asm("cvt.rn.f16x2.f32 %0, %1, %2;" : "=r"(r) : "f"(hi), "f"(lo));
    return r;
}
// packed exp2 on the SFU (2 exps per MUFU op); logits pre-scaled by log2(e)
__device__ __forceinline__ uint32_t ex2_f16x2(uint32_t x) {
    uint32_t r;
    asm("ex2.approx.f16x2 %0, %1;" : "=r"(r) : "r"(x));
    return r;
}

// float2 from packed half2 register
__device__ __forceinline__ float2 h2f2(uint32_t h) {
    return __half22float2(*reinterpret_cast<__half2*>(&h));
}

// ---------------- pre-kernel: build padded fp16 W image once ----------------
__global__ void prep_w_kernel(const float* __restrict__ weight) {
    const int i = blockIdx.x * blockDim.x + threadIdx.x;
    if (i >= BHALF) return;
    const int r = i / 56;             // padded row (56 halfs per row)
    const int c = i - r * 56;         // k index
    const int a = r / JPAD;
    const int j = r - a * JPAD;
    float v = 0.0f;
    if (j < KK && c < KK)
        v = __ldg(weight + (a * KK + j) * KK + c) * LOG2E;
    reinterpret_cast<__half*>(g_wf16)[i] = __float2half_rn(v);
}

// one action's GEMM block: 9 LDSM + 18 MMA into d[6][4]
__device__ __forceinline__ void action_mma(float d[6][4], const uint32_t Af[3][4],
                                           uint32_t bB, uint32_t aoff) {
#pragma unroll
    for (int nt = 0; nt < 6; nt++)
#pragma unroll
        for (int e = 0; e < 4; e++) d[nt][e] = 0.0f;
#pragma unroll
    for (int kt = 0; kt < 3; kt++) {
        uint32_t bf[3][4];
#pragma unroll
        for (int ntp = 0; ntp < 3; ntp++)
            ldsm_x4(bf[ntp], bB + aoff + (uint32_t)(ntp * 16 * BSTR + kt * 32));
#pragma unroll
        for (int ntp = 0; ntp < 3; ntp++) {
            mma_f16(d[2 * ntp],     Af[kt], bf[ntp][0], bf[ntp][1]);
            mma_f16(d[2 * ntp + 1], Af[kt], bf[ntp][2], bf[ntp][3]);
        }
    }
}

// one action's epilogue: packed f16x2 exp2, weighted sums, quad reduce, max
__device__ __forceinline__ void action_epi(const float d[6][4],
                                           const float2 PA[6], const float2 PB[6],
                                           float m50, float m51,
                                           float& vmax0, float& vmax1) {
    float sa[6], sb[6], qa[6], qb[6];
#pragma unroll
    for (int nt = 0; nt < 6; nt++) {
        const uint32_t ea = ex2_f16x2(pack_f16x2(d[nt][0], d[nt][1]));
        const uint32_t eb = ex2_f16x2(pack_f16x2(d[nt][2], d[nt][3]));
        const float2 eA = h2f2(ea);    // (e00, e01)
        const float2 eB = h2f2(eb);    // (e10, e11)
        float e00 = eA.x, e01 = eA.y, e10 = eB.x, e11 = eB.y;
        if (nt == 5) { e00 *= m50; e01 *= m51; e10 *= m50; e11 *= m51; }
        sa[nt] = e00 + e01;
        sb[nt] = e10 + e11;
        qa[nt] = fmaf(PA[nt].x, e00, PA[nt].y * e01);
        qb[nt] = fmaf(PB[nt].x, e10, PB[nt].y * e11);
    }
    float S0 = ((sa[0] + sa[1]) + (sa[2] + sa[3])) + (sa[4] + sa[5]);
    float S1 = ((sb[0] + sb[1]) + (sb[2] + sb[3])) + (sb[4] + sb[5]);
    float q0 = ((qa[0] + qa[1]) + (qa[2] + qa[3])) + (qa[4] + qa[5]);
    float q1 = ((qb[0] + qb[1]) + (qb[2] + qb[3])) + (qb[4] + qb[5]);
#pragma unroll
    for (int m = 1; m <= 2; m <<= 1) {
        S0 += __shfl_xor_sync(0xFFFFFFFFu, S0, m);
        q0 += __shfl_xor_sync(0xFFFFFFFFu, q0, m);
        S1 += __shfl_xor_sync(0xFFFFFFFFu, S1, m);
        q1 += __shfl_xor_sync(0xFFFFFFFFu, q1, m);
    }
    vmax0 = fmaxf(vmax0, __fdividef(q0, S0));
    vmax1 = fmaxf(vmax1, __fdividef(q1, S1));
}

__global__ __launch_bounds__(512, 1)
void vi_mma_kernel(const float* __restrict__ values,
                   const float* __restrict__ rewards,
                   float* __restrict__ out)
{
    extern __shared__ char smem[];
    const int tid  = threadIdx.x;
    const int wm   = tid >> 5;        // warp id = m-tile (0..15)
    const int lane = tid & 31;
    const int lq   = lane & 3;        // quad lane
    const int lr   = lane >> 2;       // 0..7

    // CTA = 2 image rows (128 is even -> same batch)
    const int rbase = blockIdx.x * 2;
    const int b  = rbase >> 7;
    const int h0 = rbase & 127;

    // No zero-fill needed: A rows fully written by builders (incl. k=45..47
    // zeros; bytes 96..111 never read); B image arrives pre-padded.
    if (tid < MPIX) {
        // ---- patch builders: pixel p = tid -> (h0 + p/128, p%128) ----
        const int p = tid;
        const int h = h0 + (p >> 7);
        const int w = p & 127;
        float pv[KPAD];
#pragma unroll
        for (int k = KK; k < KPAD; k++) pv[k] = 0.0f;
#pragma unroll
        for (int i = 0; i < 5; i++) {
            const float* src = (i < RDIM)
                ? rewards + (size_t)(b * RDIM + i) * (H_ * W_)
                : values  + (size_t)b * (H_ * W_);
#pragma unroll
            for (int dh = 0; dh < 3; dh++) {
                const int hh = h + dh - 1;
                const bool hok = (hh >= 0) & (hh < H_);
#pragma unroll
                for (int dw = 0; dw < 3; dw++) {
                    const int ww = w + dw - 1;
                    const bool ok = hok & (ww >= 0) & (ww < W_);
                    pv[i * 9 + dh * 3 + dw] = ok ? __ldg(src + hh * W_ + ww) : 0.0f;
                }
            }
        }
#pragma unroll
        for (int k2 = 0; k2 < KPAD / 2; k2++) {
            const __half2 hx = __floats2half2_rn(pv[2 * k2], pv[2 * k2 + 1]);
            *reinterpret_cast<__half2*>(smem + OFF_A + p * ASTR + k2 * 4) = hx;
        }
    } else {
        // ---- B copy: pre-built fp16 image, pure vectorized copy ----
        const uint4* src = reinterpret_cast<const uint4*>(g_wf16);
        uint4* dst = reinterpret_cast<uint4*>(smem + OFF_B);
        for (int i = tid - MPIX; i < SZ_B / 16; i += 256)
            dst[i] = __ldg(src + i);
    }
    __syncthreads();

    // ---- preload A fragments (3 k-tiles) ----
    const int r0 = wm * 16 + lr;
    uint32_t Af[3][4];
#pragma unroll
    for (int kt = 0; kt < 3; kt++) {
        const int base = r0 * ASTR + kt * 32 + lq * 4;
        Af[kt][0] = *reinterpret_cast<uint32_t*>(smem + OFF_A + base);
        Af[kt][1] = *reinterpret_cast<uint32_t*>(smem + OFF_A + base + 8 * ASTR);
        Af[kt][2] = *reinterpret_cast<uint32_t*>(smem + OFF_A + base + 16);
        Af[kt][3] = *reinterpret_cast<uint32_t*>(smem + OFF_A + base + 8 * ASTR + 16);
    }

    // ---- hoist epilogue patch values to fp32 once ----
    float2 PA[6], PB[6];
#pragma unroll
    for (int nt = 0; nt < 6; nt++) {
        const int t = nt >> 1;
        const int o = (nt & 1) << 1;
        PA[nt] = h2f2(Af[t][o]);       // row r0
        PB[nt] = h2f2(Af[t][o + 1]);   // row r0+8
    }

    // ---- per-lane ldmatrix base address for B fragments ----
    const uint32_t sbase = smem_u32(smem);
    const int g = lane >> 3, gr = lane & 7;
    const uint32_t bB = sbase + OFF_B
                      + (uint32_t)(((g >> 1) * 8 + gr) * BSTR + (g & 1) * 16);

    // masks for n-tile 5 (j = 40 + 2*lq + c must be < 45)
    const float m50 = (2 * lq + 0 < 5) ? 1.0f : 0.0f;
    const float m51 = (2 * lq + 1 < 5) ? 1.0f : 0.0f;

    float vmax0 = -3.4e38f, vmax1 = -3.4e38f;

    // ---- paired-action loop: two independent epilogue chains per pair ----
#pragma unroll
    for (int ap = 0; ap < ACT / 2; ap++) {
        float d0[6][4], d1[6][4];
        action_mma(d0, Af, bB, (uint32_t)((2 * ap)     * (JPAD * BSTR)));
        action_mma(d1, Af, bB, (uint32_t)((2 * ap + 1) * (JPAD * BSTR)));
        action_epi(d0, PA, PB, m50, m51, vmax0, vmax1);
        action_epi(d1, PA, PB, m50, m51, vmax0, vmax1);
    }

    if (lq == 0) {
        const int p0i = r0;
        const int p1i = r0 + 8;
        out[((size_t)(b * H_) + h0 + (p0i >> 7)) * W_ + (p0i & 127)] = vmax0;
        out[((size_t)(b * H_) + h0 + (p1i >> 7)) * W_ + (p1i & 127)] = vmax1;
    }
}

extern "C" void kernel_launch(void* const* d_in, const int* in_sizes, int n_in,
                              void* d_out, int out_size)
{
    (void)in_sizes; (void)n_in; (void)out_size;
    const float* values  = (const float*)d_in[0];  // [16,128,128]
    const float* rewards = (const float*)d_in[1];  // [16,4,128,128]
    const float* weight  = (const float*)d_in[2];  // [360,5,3,3]
    float* out = (float*)d_out;                    // [16,128,128]

    cudaFuncSetAttribute(vi_mma_kernel, cudaFuncAttributeMaxDynamicSharedMemorySize,
                         SM_END);

    // 1) build padded fp16 W image (tiny)
    prep_w_kernel<<<(BHALF + 255) / 256, 256>>>(weight);
    // 2) main kernel: 1024 CTAs x 512 threads, 2 image rows per CTA
    vi_mma_kernel<<<B_ * H_ / 2, 512, SM_END>>>(values, rewards, out);
}

// round 17
// speedup vs baseline: 1.1791x; 1.1791x over previous
#include <cuda_runtime.h>
#include <cuda_fp16.h>
#include <cstdint>

// Shapes
#define B_    16
#define H_    128
#define W_    128
#define RDIM  4
#define ACT   8
#define KK    45      // logit/patch dim
#define KPAD  48      // padded K (3 k-tiles of 16)
#define JPAD  48      // padded rows per action (6 n-tiles of 8)
#define MPIX  256     // pixels per CTA (2 image rows)

// SMEM layout (bytes). Strides chosen for conflict-free fragment access.
#define ASTR   112                  // fp16 A row stride
#define BSTR   112                  // fp16 B row stride (56 halfs)
#define OFF_A  0
#define OFF_B  (OFF_A + MPIX*ASTR)  // 28672
#define SZ_B   (ACT*JPAD*BSTR)      // 43008
#define SM_END (OFF_B + SZ_B)       // 71680 B
#define BHALF  (SZ_B/2)             // 21504 halfs

#define LOG2E 1.4426950408889634f

// Pre-built padded fp16 weight image (exact SMEM B-region layout)
__device__ __align__(16) unsigned char g_wf16[SZ_B];

__device__ __forceinline__ void mma_f16(float d[4], const uint32_t a[4],
                                        uint32_t b0, uint32_t b1) {
    asm volatile(
        "mma.sync.aligned.m16n8k16.row.col.f32.f16.f16.f32 "
        "{%0,%1,%2,%3}, {%4,%5,%6,%7}, {%8,%9}, {%0,%1,%2,%3};"
        : "+f"(d[0]), "+f"(d[1]), "+f"(d[2]), "+f"(d[3])
        : "r"(a[0]), "r"(a[1]), "r"(a[2]), "r"(a[3]), "r"(b0), "r"(b1));
}

__device__ __forceinline__ void ldsm_x4(uint32_t r[4], uint32_t addr) {
    asm volatile("ldmatrix.sync.aligned.m8n8.x4.shared.b16 {%0,%1,%2,%3}, [%4];"
                 : "=r"(r[0]), "=r"(r[1]), "=r"(r[2]), "=r"(r[3]) : "r"(addr));
}

__device__ __forceinline__ uint32_t smem_u32(const void* p) {
    uint32_t a;
    asm("{ .reg .u64 t; cvta.to.shared.u64 t, %1; cvt.u32.u64 %0, t; }" : "=r"(a) : "l"(p));
    return a;
}

// exp2 on the SFU; logits are pre-scaled by log2(e) via the weights
__device__ __forceinline__ float ex2f(float x) {
    float r;
    asm("ex2.approx.ftz.f32 %0, %1;" : "=f"(r) : "f"(x));
    return r;
}

// float2 from packed half2 register
__device__ __forceinline__ float2 h2f2(uint32_t h) {
    return __half22float2(*reinterpret_cast<__half2*>(&h));
}

// ---------------- pre-kernel: build padded fp16 W image once ----------------
__global__ void prep_w_kernel(const float* __restrict__ weight) {
    const int i = blockIdx.x * blockDim.x + threadIdx.x;
    if (i >= BHALF) return;
    const int r = i / 56;             // padded row (56 halfs per row)
    const int c = i - r * 56;         // k index
    const int a = r / JPAD;
    const int j = r - a * JPAD;
    float v = 0.0f;
    if (j < KK && c < KK)
        v = __ldg(weight + (a * KK + j) * KK + c) * LOG2E;
    reinterpret_cast<__half*>(g_wf16)[i] = __float2half_rn(v);
}

// one m-tile's epilogue: f32 ex2, patch from A frags, tree sums, quad reduce
__device__ __forceinline__ void action_epi(const float d[6][4],
                                           const uint32_t Af[3][4],
                                           float m50, float m51,
                                           float& vmax0, float& vmax1) {
    float sa[6], sb[6], qa[6], qb[6];
#pragma unroll
    for (int nt = 0; nt < 6; nt++) {
        const int t = nt >> 1;
        const int o = (nt & 1) << 1;
        const float2 pa = h2f2(Af[t][o]);      // row r0
        const float2 pb = h2f2(Af[t][o + 1]);  // row r0+8
        float e00 = ex2f(d[nt][0]);
        float e01 = ex2f(d[nt][1]);
        float e10 = ex2f(d[nt][2]);
        float e11 = ex2f(d[nt][3]);
        if (nt == 5) { e00 *= m50; e01 *= m51; e10 *= m50; e11 *= m51; }
        sa[nt] = e00 + e01;
        sb[nt] = e10 + e11;
        qa[nt] = fmaf(pa.x, e00, pa.y * e01);
        qb[nt] = fmaf(pb.x, e10, pb.y * e11);
    }
    float S0 = ((sa[0] + sa[1]) + (sa[2] + sa[3])) + (sa[4] + sa[5]);
    float S1 = ((sb[0] + sb[1]) + (sb[2] + sb[3])) + (sb[4] + sb[5]);
    float q0 = ((qa[0] + qa[1]) + (qa[2] + qa[3])) + (qa[4] + qa[5]);
    float q1 = ((qb[0] + qb[1]) + (qb[2] + qb[3])) + (qb[4] + qb[5]);
#pragma unroll
    for (int m = 1; m <= 2; m <<= 1) {
        S0 += __shfl_xor_sync(0xFFFFFFFFu, S0, m);
        q0 += __shfl_xor_sync(0xFFFFFFFFu, q0, m);
        S1 += __shfl_xor_sync(0xFFFFFFFFu, S1, m);
        q1 += __shfl_xor_sync(0xFFFFFFFFu, q1, m);
    }
    vmax0 = fmaxf(vmax0, __fdividef(q0, S0));
    vmax1 = fmaxf(vmax1, __fdividef(q1, S1));
}

__global__ __launch_bounds__(256, 2)   // 16 warps/SM, regs capped at 128
void vi_mma_kernel(const float* __restrict__ values,
                   const float* __restrict__ rewards,
                   float* __restrict__ out)
{
    extern __shared__ char smem[];
    const int tid  = threadIdx.x;
    const int wm   = tid >> 5;        // warp id (0..7): owns m-tiles 2wm, 2wm+1
    const int lane = tid & 31;
    const int lq   = lane & 3;        // quad lane
    const int lr   = lane >> 2;       // 0..7

    // CTA = 2 image rows (128 is even -> same batch)
    const int rbase = blockIdx.x * 2;
    const int b  = rbase >> 7;
    const int h0 = rbase & 127;

    // ---- patch builders: every thread builds pixel p = tid ----
    {
        const int p = tid;
        const int h = h0 + (p >> 7);
        const int w = p & 127;
        float pv[KPAD];
#pragma unroll
        for (int k = KK; k < KPAD; k++) pv[k] = 0.0f;
#pragma unroll
        for (int i = 0; i < 5; i++) {
            const float* src = (i < RDIM)
                ? rewards + (size_t)(b * RDIM + i) * (H_ * W_)
                : values  + (size_t)b * (H_ * W_);
#pragma unroll
            for (int dh = 0; dh < 3; dh++) {
                const int hh = h + dh - 1;
                const bool hok = (hh >= 0) & (hh < H_);
#pragma unroll
                for (int dw = 0; dw < 3; dw++) {
                    const int ww = w + dw - 1;
                    const bool ok = hok & (ww >= 0) & (ww < W_);
                    pv[i * 9 + dh * 3 + dw] = ok ? __ldg(src + hh * W_ + ww) : 0.0f;
                }
            }
        }
#pragma unroll
        for (int k2 = 0; k2 < KPAD / 2; k2++) {
            const __half2 hx = __floats2half2_rn(pv[2 * k2], pv[2 * k2 + 1]);
            *reinterpret_cast<__half2*>(smem + OFF_A + p * ASTR + k2 * 4) = hx;
        }
    }
    // ---- B copy: pre-built fp16 image, pure vectorized copy ----
    {
        const uint4* src = reinterpret_cast<const uint4*>(g_wf16);
        uint4* dst = reinterpret_cast<uint4*>(smem + OFF_B);
        for (int i = tid; i < SZ_B / 16; i += 256)
            dst[i] = __ldg(src + i);
    }
    __syncthreads();

    // ---- preload A fragments for BOTH m-tiles (3 k-tiles each) ----
    const int ra = wm * 32 + lr;          // m-tile 0 fragment row
    const int rb = ra + 16;               // m-tile 1 fragment row
    uint32_t Afa[3][4], Afb[3][4];
#pragma unroll
    for (int kt = 0; kt < 3; kt++) {
        const int ka = ra * ASTR + kt * 32 + lq * 4;
        Afa[kt][0] = *reinterpret_cast<uint32_t*>(smem + OFF_A + ka);
        Afa[kt][1] = *reinterpret_cast<uint32_t*>(smem + OFF_A + ka + 8 * ASTR);
        Afa[kt][2] = *reinterpret_cast<uint32_t*>(smem + OFF_A + ka + 16);
        Afa[kt][3] = *reinterpret_cast<uint32_t*>(smem + OFF_A + ka + 8 * ASTR + 16);
        const int kb = rb * ASTR + kt * 32 + lq * 4;
        Afb[kt][0] = *reinterpret_cast<uint32_t*>(smem + OFF_A + kb);
        Afb[kt][1] = *reinterpret_cast<uint32_t*>(smem + OFF_A + kb + 8 * ASTR);
        Afb[kt][2] = *reinterpret_cast<uint32_t*>(smem + OFF_A + kb + 16);
        Afb[kt][3] = *reinterpret_cast<uint32_t*>(smem + OFF_A + kb + 8 * ASTR + 16);
    }

    // ---- per-lane ldmatrix base address for B fragments ----
    const uint32_t sbase = smem_u32(smem);
    const int g = lane >> 3, gr = lane & 7;
    const uint32_t bB = sbase + OFF_B
                      + (uint32_t)(((g >> 1) * 8 + gr) * BSTR + (g & 1) * 16);

    // masks for n-tile 5 (j = 40 + 2*lq + c must be < 45)
    const float m50 = (2 * lq + 0 < 5) ? 1.0f : 0.0f;
    const float m51 = (2 * lq + 1 < 5) ? 1.0f : 0.0f;

    float vm0 = -3.4e38f, vm1 = -3.4e38f, vm2 = -3.4e38f, vm3 = -3.4e38f;

#pragma unroll 1
    for (int a = 0; a < ACT; a++) {
        float d0[6][4], d1[6][4];
#pragma unroll
        for (int nt = 0; nt < 6; nt++)
#pragma unroll
            for (int e = 0; e < 4; e++) { d0[nt][e] = 0.0f; d1[nt][e] = 0.0f; }

        const uint32_t aoff = (uint32_t)(a * (JPAD * BSTR));
#pragma unroll
        for (int kt = 0; kt < 3; kt++) {
            uint32_t bf[3][4];
#pragma unroll
            for (int ntp = 0; ntp < 3; ntp++)
                ldsm_x4(bf[ntp], bB + aoff + (uint32_t)(ntp * 16 * BSTR + kt * 32));
            // each B fragment feeds 4 MMAs (2 n-tiles x 2 m-tiles)
#pragma unroll
            for (int ntp = 0; ntp < 3; ntp++) {
                mma_f16(d0[2 * ntp],     Afa[kt], bf[ntp][0], bf[ntp][1]);
                mma_f16(d1[2 * ntp],     Afb[kt], bf[ntp][0], bf[ntp][1]);
                mma_f16(d0[2 * ntp + 1], Afa[kt], bf[ntp][2], bf[ntp][3]);
                mma_f16(d1[2 * ntp + 1], Afb[kt], bf[ntp][2], bf[ntp][3]);
            }
        }

        // two independent epilogue chains (one per m-tile)
        action_epi(d0, Afa, m50, m51, vm0, vm1);
        action_epi(d1, Afb, m50, m51, vm2, vm3);
    }

    if (lq == 0) {
        // pixels: ra, ra+8 (m-tile 0); rb, rb+8 (m-tile 1)
        const int px[4] = { ra, ra + 8, rb, rb + 8 };
        const float vv[4] = { vm0, vm1, vm2, vm3 };
#pragma unroll
        for (int i = 0; i < 4; i++) {
            const int p = px[i];
            out[((size_t)(b * H_) + h0 + (p >> 7)) * W_ + (p & 127)] = vv[i];
        }
    }
}

extern "C" void kernel_launch(void* const* d_in, const int* in_sizes, int n_in,
                              void* d_out, int out_size)
{
    (void)in_sizes; (void)n_in; (void)out_size;
    const float* values  = (const float*)d_in[0];  // [16,128,128]
    const float* rewards = (const float*)d_in[1];  // [16,4,128,128]
    const float* weight  = (const float*)d_in[2];  // [360,5,3,3]
    float* out = (float*)d_out;                    // [16,128,128]

    cudaFuncSetAttribute(vi_mma_kernel, cudaFuncAttributeMaxDynamicSharedMemorySize,
                         SM_END);

    // 1) build padded fp16 W image (tiny)
    prep_w_kernel<<<(BHALF + 255) / 256, 256>>>(weight);
    // 2) main kernel: 1024 CTAs x 256 threads, 2 image rows per CTA,
    //    each warp = 2 m-tiles (32 pixels)
    vi_mma_kernel<<<B_ * H_ / 2, 256, SM_END>>>(values, rewards, out);
}